// round 5
// baseline (speedup 1.0000x reference)
#include <cuda_runtime.h>
#include <cuda_bf16.h>
#include <cstdint>

// Problem constants
#define SEQ     2048
#define HIDDEN  2048
#define HEADS   32
#define GROUPS  8
#define HEAD_D  64
#define KV_DIM  512   // GROUPS * HEAD_D
#define QPG     4     // HEADS / GROUPS

// Scratch (device globals: no allocation allowed)
__device__ float g_Q[SEQ * HIDDEN];
__device__ float g_K[SEQ * KV_DIM];
__device__ float g_V[SEQ * KV_DIM];
__device__ float g_A[SEQ * HIDDEN];

__device__ __forceinline__ uint32_t f2tf32(float f) {
    uint32_t u;
    asm("cvt.rna.tf32.f32 %0, %1;\n" : "=r"(u) : "f"(f));
    return u;
}

__device__ __forceinline__ void mma_tf32(float* c, const uint32_t* a, const uint32_t* b) {
    asm volatile(
        "mma.sync.aligned.m16n8k8.row.col.f32.tf32.tf32.f32 "
        "{%0,%1,%2,%3}, {%4,%5,%6,%7}, {%8,%9}, {%0,%1,%2,%3};\n"
        : "+f"(c[0]), "+f"(c[1]), "+f"(c[2]), "+f"(c[3])
        : "r"(a[0]), "r"(a[1]), "r"(a[2]), "r"(a[3]), "r"(b[0]), "r"(b[1]));
}

// ---------------------------------------------------------------------------
// TF32 GEMM core: C[:,N] tile = A[128,K] @ B[K,128] + bias.  256 threads.
// ---------------------------------------------------------------------------
#define AS_LD 20
#define BS_LD 136

__device__ __forceinline__ void gemm_body(
    const float* __restrict__ A, const float* __restrict__ B,
    const float* __restrict__ bias, float* __restrict__ C,
    int N, int K, int blockRow, int blockCol)
{
    __shared__ uint32_t As[2][128][AS_LD];
    __shared__ uint32_t Bs[2][16][BS_LD];

    const int tid  = threadIdx.x;
    const int warp = tid >> 5;
    const int lane = tid & 31;
    const int gid  = lane >> 2;
    const int tg   = lane & 3;

    const int mBase = (warp & 1) * 64;
    const int nBase = (warp >> 1) * 32;

    const float* Ablk = A + (size_t)blockRow * 128 * K;
    const float* Bblk = B + (size_t)blockCol * 128;

    float acc[4][4][4];
#pragma unroll
    for (int i = 0; i < 4; i++)
#pragma unroll
        for (int j = 0; j < 4; j++)
#pragma unroll
            for (int r = 0; r < 4; r++) acc[i][j][r] = 0.f;

    const int T = K / 16;
    float4 aR[2], bR[2];

    auto ldg_tile = [&](int kt) {
#pragma unroll
        for (int p = 0; p < 2; p++) {
            int s = tid + p * 256;
            aR[p] = *(const float4*)&Ablk[(size_t)(s >> 2) * K + kt + (s & 3) * 4];
            bR[p] = *(const float4*)&Bblk[(size_t)(kt + (s >> 5)) * N + (s & 31) * 4];
        }
    };
    auto sts_tile = [&](int st) {
#pragma unroll
        for (int p = 0; p < 2; p++) {
            int s = tid + p * 256;
            uint4 av = make_uint4(f2tf32(aR[p].x), f2tf32(aR[p].y), f2tf32(aR[p].z), f2tf32(aR[p].w));
            uint4 bv = make_uint4(f2tf32(bR[p].x), f2tf32(bR[p].y), f2tf32(bR[p].z), f2tf32(bR[p].w));
            *(uint4*)&As[st][s >> 2][(s & 3) * 4]  = av;
            *(uint4*)&Bs[st][s >> 5][(s & 31) * 4] = bv;
        }
    };

    ldg_tile(0);
    sts_tile(0);
    __syncthreads();

    for (int t = 0; t < T; t++) {
        if (t + 1 < T) ldg_tile((t + 1) * 16);

        const int st = t & 1;
#pragma unroll
        for (int kc = 0; kc < 16; kc += 8) {
            uint32_t af[4][4];
#pragma unroll
            for (int mt = 0; mt < 4; mt++) {
                int r0 = mBase + mt * 16 + gid;
                af[mt][0] = As[st][r0    ][kc + tg    ];
                af[mt][1] = As[st][r0 + 8][kc + tg    ];
                af[mt][2] = As[st][r0    ][kc + tg + 4];
                af[mt][3] = As[st][r0 + 8][kc + tg + 4];
            }
            uint32_t bf[4][2];
#pragma unroll
            for (int nt = 0; nt < 4; nt++) {
                int c0 = nBase + nt * 8 + gid;
                bf[nt][0] = Bs[st][kc + tg    ][c0];
                bf[nt][1] = Bs[st][kc + tg + 4][c0];
            }
#pragma unroll
            for (int mt = 0; mt < 4; mt++)
#pragma unroll
                for (int nt = 0; nt < 4; nt++)
                    mma_tf32(acc[mt][nt], af[mt], bf[nt]);
        }

        if (t + 1 < T) sts_tile((t + 1) & 1);
        __syncthreads();
    }

#pragma unroll
    for (int mt = 0; mt < 4; mt++) {
#pragma unroll
        for (int nt = 0; nt < 4; nt++) {
            int row = blockRow * 128 + mBase + mt * 16 + gid;
            int col = blockCol * 128 + nBase + nt * 8 + tg * 2;
            float bx = bias[col], by = bias[col + 1];
            *(float2*)&C[(size_t)row * N + col]       = make_float2(acc[mt][nt][0] + bx, acc[mt][nt][1] + by);
            *(float2*)&C[(size_t)(row + 8) * N + col] = make_float2(acc[mt][nt][2] + bx, acc[mt][nt][3] + by);
        }
    }
}

__global__ __launch_bounds__(256) void tf32_gemm_bias_kernel(
    const float* __restrict__ A, const float* __restrict__ B,
    const float* __restrict__ bias, float* __restrict__ C, int N, int K)
{
    gemm_body(A, B, bias, C, N, K, blockIdx.y, blockIdx.x);
}

// Fused QKV projection: grid.x = 16(Q) + 4(K) + 4(V) = 24, grid.y = 16.
__global__ __launch_bounds__(256) void tf32_gemm_qkv_kernel(
    const float* __restrict__ x,
    const float* __restrict__ Wq, const float* __restrict__ bq, float* __restrict__ Qo,
    const float* __restrict__ Wk, const float* __restrict__ bk, float* __restrict__ Ko,
    const float* __restrict__ Wv, const float* __restrict__ bv, float* __restrict__ Vo)
{
    int bx = blockIdx.x;
    if (bx < 16)      gemm_body(x, Wq, bq, Qo, HIDDEN, HIDDEN, blockIdx.y, bx);
    else if (bx < 20) gemm_body(x, Wk, bk, Ko, KV_DIM, HIDDEN, blockIdx.y, bx - 16);
    else              gemm_body(x, Wv, bv, Vo, KV_DIM, HIDDEN, blockIdx.y, bx - 20);
}

// ---------------------------------------------------------------------------
// Tensor-core flash attention v2 (causal, GQA).
// grid = (SEQ/128, HEADS), block = 128 (4 warps). Warp w owns 32 q-rows
// (2 m-tiles of 16). P never touches smem: C-frag -> A-frag via shuffles.
// Ks pad 68 (4*gid+tg banks), Vs pad 72 (8*tg+gid banks): conflict-free.
// ---------------------------------------------------------------------------
#define KPAD 68
#define VPAD 72

__device__ __forceinline__ float shsel(float v0, float v1, int src, int odd) {
    float a = __shfl_sync(0xffffffffu, v0, src);
    float b = __shfl_sync(0xffffffffu, v1, src);
    return odd ? b : a;
}

__global__ __launch_bounds__(128) void flash_tc2_kernel(
    const float* __restrict__ Q, const float* __restrict__ K,
    const float* __restrict__ V, float* __restrict__ O)
{
    __shared__ uint32_t Ks[64][KPAD];
    __shared__ uint32_t Vs[64][VPAD];

    const int qblk = gridDim.x - 1 - blockIdx.x;   // long blocks first
    const int h    = blockIdx.y;
    const int g    = h / QPG;
    const int q0   = qblk * 128;

    const int tid  = threadIdx.x;
    const int warp = tid >> 5;
    const int lane = tid & 31;
    const int gid  = lane >> 2;
    const int tg   = lane & 3;

    // Q fragments (2 m-tiles), converted once, pre-scaled by 1/8
    uint32_t qa[2][8][4];
#pragma unroll
    for (int mt = 0; mt < 2; mt++) {
        const float* QbA = Q + (size_t)(q0 + warp * 32 + mt * 16 + gid) * HIDDEN + h * HEAD_D;
        const float* QbB = QbA + 8 * HIDDEN;
#pragma unroll
        for (int ks = 0; ks < 8; ks++) {
            int c = ks * 8 + tg;
            qa[mt][ks][0] = f2tf32(QbA[c]     * 0.125f);
            qa[mt][ks][1] = f2tf32(QbB[c]     * 0.125f);
            qa[mt][ks][2] = f2tf32(QbA[c + 4] * 0.125f);
            qa[mt][ks][3] = f2tf32(QbB[c + 4] * 0.125f);
        }
    }

    float accO[2][8][4];
#pragma unroll
    for (int mt = 0; mt < 2; mt++)
#pragma unroll
        for (int nt = 0; nt < 8; nt++)
#pragma unroll
            for (int r = 0; r < 4; r++) accO[mt][nt][r] = 0.f;
    float mA[2] = {-1e30f, -1e30f}, mB[2] = {-1e30f, -1e30f};
    float lA[2] = {0.f, 0.f},       lB[2] = {0.f, 0.f};

    const int lrow  = tid & 63;
    const int lhalf = (tid >> 6) * 32;
    const int ntiles = 2 * qblk + 2;
    const int wmin   = q0 + warp * 32;        // min row this warp owns
    const int wmax   = wmin + 31;             // max row this warp owns

    for (int t = 0; t < ntiles; t++) {
        const int j0 = t * 64;
        __syncthreads();   // prior tile's smem reads complete

        {   // cooperative K/V tile load -> tf32 smem
            const float* kp = K + (size_t)(j0 + lrow) * KV_DIM + g * HEAD_D + lhalf;
            const float* vp = V + (size_t)(j0 + lrow) * KV_DIM + g * HEAD_D + lhalf;
#pragma unroll
            for (int i = 0; i < 8; i++) {
                float4 kv = *(const float4*)&kp[i * 4];
                float4 vv = *(const float4*)&vp[i * 4];
                *(uint4*)&Ks[lrow][lhalf + i * 4] =
                    make_uint4(f2tf32(kv.x), f2tf32(kv.y), f2tf32(kv.z), f2tf32(kv.w));
                *(uint4*)&Vs[lrow][lhalf + i * 4] =
                    make_uint4(f2tf32(vv.x), f2tf32(vv.y), f2tf32(vv.z), f2tf32(vv.w));
            }
        }
        __syncthreads();

        if (j0 > wmax) continue;   // tile fully masked for this warp

        // S = Q @ K^T : 32 rows x 64 keys
        float accS[2][8][4];
#pragma unroll
        for (int mt = 0; mt < 2; mt++)
#pragma unroll
            for (int nt = 0; nt < 8; nt++)
#pragma unroll
                for (int r = 0; r < 4; r++) accS[mt][nt][r] = 0.f;

#pragma unroll
        for (int ks = 0; ks < 8; ks++) {
#pragma unroll
            for (int nt = 0; nt < 8; nt++) {
                uint32_t b[2] = { Ks[nt * 8 + gid][ks * 8 + tg],
                                  Ks[nt * 8 + gid][ks * 8 + tg + 4] };
                mma_tf32(accS[0][nt], qa[0][ks], b);
                mma_tf32(accS[1][nt], qa[1][ks], b);
            }
        }

        // causal mask on boundary tiles
        if (j0 + 63 > wmin) {
#pragma unroll
            for (int mt = 0; mt < 2; mt++) {
                int rA = wmin + mt * 16 + gid;
#pragma unroll
                for (int nt = 0; nt < 8; nt++) {
                    int k0 = j0 + nt * 8 + 2 * tg;
                    if (k0     > rA)     accS[mt][nt][0] = -1e30f;
                    if (k0 + 1 > rA)     accS[mt][nt][1] = -1e30f;
                    if (k0     > rA + 8) accS[mt][nt][2] = -1e30f;
                    if (k0 + 1 > rA + 8) accS[mt][nt][3] = -1e30f;
                }
            }
        }

        // online softmax (per m-tile; rows A = regs 0/1, rows B = regs 2/3)
#pragma unroll
        for (int mt = 0; mt < 2; mt++) {
            float mx0 = -1e30f, mx1 = -1e30f;
#pragma unroll
            for (int nt = 0; nt < 8; nt++) {
                mx0 = fmaxf(mx0, fmaxf(accS[mt][nt][0], accS[mt][nt][1]));
                mx1 = fmaxf(mx1, fmaxf(accS[mt][nt][2], accS[mt][nt][3]));
            }
            mx0 = fmaxf(mx0, __shfl_xor_sync(0xffffffffu, mx0, 1));
            mx0 = fmaxf(mx0, __shfl_xor_sync(0xffffffffu, mx0, 2));
            mx1 = fmaxf(mx1, __shfl_xor_sync(0xffffffffu, mx1, 1));
            mx1 = fmaxf(mx1, __shfl_xor_sync(0xffffffffu, mx1, 2));

            float mn0 = fmaxf(mA[mt], mx0), mn1 = fmaxf(mB[mt], mx1);
            float sc0 = __expf(mA[mt] - mn0), sc1 = __expf(mB[mt] - mn1);

            float s0 = 0.f, s1 = 0.f;
#pragma unroll
            for (int nt = 0; nt < 8; nt++) {
                accS[mt][nt][0] = __expf(accS[mt][nt][0] - mn0);
                accS[mt][nt][1] = __expf(accS[mt][nt][1] - mn0);
                accS[mt][nt][2] = __expf(accS[mt][nt][2] - mn1);
                accS[mt][nt][3] = __expf(accS[mt][nt][3] - mn1);
                s0 += accS[mt][nt][0] + accS[mt][nt][1];
                s1 += accS[mt][nt][2] + accS[mt][nt][3];
            }
            s0 += __shfl_xor_sync(0xffffffffu, s0, 1);
            s0 += __shfl_xor_sync(0xffffffffu, s0, 2);
            s1 += __shfl_xor_sync(0xffffffffu, s1, 1);
            s1 += __shfl_xor_sync(0xffffffffu, s1, 2);
            lA[mt] = lA[mt] * sc0 + s0;
            lB[mt] = lB[mt] * sc1 + s1;
            mA[mt] = mn0;
            mB[mt] = mn1;
#pragma unroll
            for (int nt = 0; nt < 8; nt++) {
                accO[mt][nt][0] *= sc0;
                accO[mt][nt][1] *= sc0;
                accO[mt][nt][2] *= sc1;
                accO[mt][nt][3] *= sc1;
            }
        }

        // O += P @ V ; P A-fragments built from accS via shuffles
        const int s0l = gid * 4 + (tg >> 1);
        const int s1l = s0l + 2;
        const int odd = tg & 1;
#pragma unroll
        for (int c = 0; c < 8; c++) {
            uint32_t uaP[2][4];
#pragma unroll
            for (int mt = 0; mt < 2; mt++) {
                uaP[mt][0] = f2tf32(shsel(accS[mt][c][0], accS[mt][c][1], s0l, odd));
                uaP[mt][1] = f2tf32(shsel(accS[mt][c][2], accS[mt][c][3], s0l, odd));
                uaP[mt][2] = f2tf32(shsel(accS[mt][c][0], accS[mt][c][1], s1l, odd));
                uaP[mt][3] = f2tf32(shsel(accS[mt][c][2], accS[mt][c][3], s1l, odd));
            }
#pragma unroll
            for (int nt = 0; nt < 8; nt++) {
                uint32_t b[2] = { Vs[c * 8 + tg    ][nt * 8 + gid],
                                  Vs[c * 8 + tg + 4][nt * 8 + gid] };
                mma_tf32(accO[0][nt], uaP[0], b);
                mma_tf32(accO[1][nt], uaP[1], b);
            }
        }
    }

    // epilogue
#pragma unroll
    for (int mt = 0; mt < 2; mt++) {
        float inv0 = 1.f / lA[mt], inv1 = 1.f / lB[mt];
        float* Ob = O + (size_t)(q0 + warp * 32 + mt * 16 + gid) * HIDDEN + h * HEAD_D;
#pragma unroll
        for (int nt = 0; nt < 8; nt++) {
            int c = nt * 8 + 2 * tg;
            *(float2*)&Ob[c]              = make_float2(accO[mt][nt][0] * inv0, accO[mt][nt][1] * inv0);
            *(float2*)&Ob[8 * HIDDEN + c] = make_float2(accO[mt][nt][2] * inv1, accO[mt][nt][3] * inv1);
        }
    }
}

// ---------------------------------------------------------------------------
extern "C" void kernel_launch(void* const* d_in, const int* in_sizes, int n_in,
                              void* d_out, int out_size)
{
    const float* x  = (const float*)d_in[0];
    const float* Wq = (const float*)d_in[2];
    const float* bq = (const float*)d_in[3];
    const float* Wk = (const float*)d_in[4];
    const float* bk = (const float*)d_in[5];
    const float* Wv = (const float*)d_in[6];
    const float* bv = (const float*)d_in[7];
    const float* Wo = (const float*)d_in[8];
    const float* bo = (const float*)d_in[9];
    float* out = (float*)d_out;

    float* Qb; cudaGetSymbolAddress((void**)&Qb, g_Q);
    float* Kb; cudaGetSymbolAddress((void**)&Kb, g_K);
    float* Vb; cudaGetSymbolAddress((void**)&Vb, g_V);
    float* Ab; cudaGetSymbolAddress((void**)&Ab, g_A);

    tf32_gemm_qkv_kernel<<<dim3(24, SEQ / 128), dim3(256)>>>(
        x, Wq, bq, Qb, Wk, bk, Kb, Wv, bv, Vb);
    flash_tc2_kernel<<<dim3(SEQ / 128, HEADS), dim3(128)>>>(Qb, Kb, Vb, Ab);
    tf32_gemm_bias_kernel<<<dim3(HIDDEN / 128, SEQ / 128), dim3(256)>>>(
        Ab, Wo, bo, out, HIDDEN, HIDDEN);
}

// round 8
// speedup vs baseline: 1.6884x; 1.6884x over previous
#include <cuda_runtime.h>
#include <cuda_fp16.h>
#include <cstdint>

#define SEQ     2048
#define HIDDEN  2048
#define HEADS   32
#define GROUPS  8
#define HEAD_D  64
#define KV_DIM  512
#define QPG     4

__device__ float g_Q[SEQ * HIDDEN];
__device__ float g_K[SEQ * KV_DIM];
__device__ float g_V[SEQ * KV_DIM];
__device__ float g_A[SEQ * HIDDEN];

__device__ __forceinline__ uint32_t packh2(float lo, float hi) {
    __half2 h = __floats2half2_rn(lo, hi);
    return *(uint32_t*)&h;
}
__device__ __forceinline__ void mma_f16(float* c, const uint32_t* a, const uint32_t* b) {
    asm volatile(
        "mma.sync.aligned.m16n8k16.row.col.f32.f16.f16.f32 "
        "{%0,%1,%2,%3}, {%4,%5,%6,%7}, {%8,%9}, {%0,%1,%2,%3};\n"
        : "+f"(c[0]), "+f"(c[1]), "+f"(c[2]), "+f"(c[3])
        : "r"(a[0]), "r"(a[1]), "r"(a[2]), "r"(a[3]), "r"(b[0]), "r"(b[1]));
}
__device__ __forceinline__ void ldsm4(uint32_t& r0, uint32_t& r1, uint32_t& r2, uint32_t& r3, uint32_t a) {
    asm volatile("ldmatrix.sync.aligned.m8n8.x4.shared.b16 {%0,%1,%2,%3}, [%4];"
                 : "=r"(r0), "=r"(r1), "=r"(r2), "=r"(r3) : "r"(a));
}
__device__ __forceinline__ void ldsm4t(uint32_t& r0, uint32_t& r1, uint32_t& r2, uint32_t& r3, uint32_t a) {
    asm volatile("ldmatrix.sync.aligned.m8n8.x4.trans.shared.b16 {%0,%1,%2,%3}, [%4];"
                 : "=r"(r0), "=r"(r1), "=r"(r2), "=r"(r3) : "r"(a));
}

// ---------------------------------------------------------------------------
// fp16 HMMA GEMM: C[128,128]-tile = A[.,K] @ B[K,N] + bias. 256 thr, 8 warps
// (64x32 warp tiles), BK=32, double-buffered. A smem [128][40] (m-major),
// B smem [32][136] ([k][n]); a-frags ldmatrix.x4, b-frags ldmatrix.x4.trans.
// Row strides 20/68 words (=4 mod 8, odd multiple) -> ldmatrix conflict-free.
// ---------------------------------------------------------------------------
__device__ void hgemm_body(const float* __restrict__ A, const float* __restrict__ B,
                           const float* __restrict__ bias, float* __restrict__ C,
                           int N, int K, int rb, int cb)
{
    __shared__ __half As[2][128][40];
    __shared__ __half Bs[2][32][136];

    const int tid = threadIdx.x, warp = tid >> 5, lane = tid & 31;
    const int gid = lane >> 2, tg = lane & 3;
    const int mBase = (warp & 1) * 64, nBase = (warp >> 1) * 32;

    const float* Ablk = A + (size_t)rb * 128 * K;
    const float* Bblk = B + (size_t)cb * 128;

    float acc[4][4][4];
#pragma unroll
    for (int i = 0; i < 4; i++)
#pragma unroll
        for (int j = 0; j < 4; j++)
#pragma unroll
            for (int r = 0; r < 4; r++) acc[i][j][r] = 0.f;

    const int T = K / 32;
    float4 aR[4], bR[4];

    auto ldg = [&](int kt) {
#pragma unroll
        for (int p = 0; p < 4; p++) {
            int s = tid + p * 256;
            aR[p] = *(const float4*)&Ablk[(size_t)(s >> 3) * K + kt + (s & 7) * 4];
            bR[p] = *(const float4*)&Bblk[(size_t)(kt + (s >> 5)) * N + (s & 31) * 4];
        }
    };
    auto sts = [&](int st) {
#pragma unroll
        for (int p = 0; p < 4; p++) {
            int s = tid + p * 256;
            uint2 av = make_uint2(packh2(aR[p].x, aR[p].y), packh2(aR[p].z, aR[p].w));
            uint2 bv = make_uint2(packh2(bR[p].x, bR[p].y), packh2(bR[p].z, bR[p].w));
            *(uint2*)&As[st][s >> 3][(s & 7) * 4]  = av;
            *(uint2*)&Bs[st][s >> 5][(s & 31) * 4] = bv;
        }
    };

    ldg(0);
    sts(0);
    __syncthreads();

    for (int t = 0; t < T; t++) {
        if (t + 1 < T) ldg((t + 1) * 32);
        const int st = t & 1;
#pragma unroll
        for (int k0 = 0; k0 < 32; k0 += 16) {
            uint32_t af[4][4], bf[4][2];
#pragma unroll
            for (int mt = 0; mt < 4; mt++)
                ldsm4(af[mt][0], af[mt][1], af[mt][2], af[mt][3],
                      (uint32_t)__cvta_generic_to_shared(
                          &As[st][mBase + mt * 16 + (lane & 15)][k0 + (lane >> 4) * 8]));
#pragma unroll
            for (int np = 0; np < 2; np++)
                ldsm4t(bf[2 * np][0], bf[2 * np][1], bf[2 * np + 1][0], bf[2 * np + 1][1],
                       (uint32_t)__cvta_generic_to_shared(
                           &Bs[st][k0 + (lane & 15)][nBase + np * 16 + (lane >> 4) * 8]));
#pragma unroll
            for (int mt = 0; mt < 4; mt++)
#pragma unroll
                for (int nt = 0; nt < 4; nt++)
                    mma_f16(acc[mt][nt], af[mt], bf[nt]);
        }
        if (t + 1 < T) sts((t + 1) & 1);
        __syncthreads();
    }

#pragma unroll
    for (int mt = 0; mt < 4; mt++) {
#pragma unroll
        for (int nt = 0; nt < 4; nt++) {
            int row = rb * 128 + mBase + mt * 16 + gid;
            int col = cb * 128 + nBase + nt * 8 + tg * 2;
            float bx = bias[col], by = bias[col + 1];
            *(float2*)&C[(size_t)row * N + col]       = make_float2(acc[mt][nt][0] + bx, acc[mt][nt][1] + by);
            *(float2*)&C[(size_t)(row + 8) * N + col] = make_float2(acc[mt][nt][2] + bx, acc[mt][nt][3] + by);
        }
    }
}

__global__ __launch_bounds__(256) void h_qkv_kernel(
    const float* __restrict__ x,
    const float* __restrict__ Wq, const float* __restrict__ bq, float* __restrict__ Qo,
    const float* __restrict__ Wk, const float* __restrict__ bk, float* __restrict__ Ko,
    const float* __restrict__ Wv, const float* __restrict__ bv, float* __restrict__ Vo)
{
    int bx = blockIdx.x;
    if (bx < 16)      hgemm_body(x, Wq, bq, Qo, HIDDEN, HIDDEN, blockIdx.y, bx);
    else if (bx < 20) hgemm_body(x, Wk, bk, Ko, KV_DIM, HIDDEN, blockIdx.y, bx - 16);
    else              hgemm_body(x, Wv, bv, Vo, KV_DIM, HIDDEN, blockIdx.y, bx - 20);
}
__global__ __launch_bounds__(256) void h_out_kernel(
    const float* __restrict__ A, const float* __restrict__ W,
    const float* __restrict__ b, float* __restrict__ C)
{
    hgemm_body(A, W, b, C, HIDDEN, HIDDEN, blockIdx.y, blockIdx.x);
}

// ---------------------------------------------------------------------------
// fp16 flash attention (causal, GQA). grid=(SEQ/128, HEADS), block=128.
// Warp owns 32 q-rows (2 m-tiles). K/V smem as half [64][72] (stride 36 words
// = 4 mod 8, odd -> ldmatrix conflict-free). QK b-frags: ldmatrix.x4 on Ks;
// PV b-frags: ldmatrix.x4.trans on Vs. P C-frag -> A-frag is pure register
// packing under m16n8k16 layouts (no shuffles, no smem round-trip).
// ---------------------------------------------------------------------------
__global__ __launch_bounds__(128) void flash_h_kernel(
    const float* __restrict__ Q, const float* __restrict__ K,
    const float* __restrict__ V, float* __restrict__ O)
{
    __shared__ __half Ks[64][72];
    __shared__ __half Vs[64][72];

    const int qblk = gridDim.x - 1 - blockIdx.x;   // long blocks first
    const int h = blockIdx.y, g = h / QPG, q0 = qblk * 128;
    const int tid = threadIdx.x, warp = tid >> 5, lane = tid & 31;
    const int gid = lane >> 2, tg = lane & 3;

    // Q a-frags: [mt][kstep][4], pre-scaled by 1/8, packed fp16
    uint32_t qa[2][4][4];
#pragma unroll
    for (int mt = 0; mt < 2; mt++) {
        const float* QbA = Q + (size_t)(q0 + warp * 32 + mt * 16 + gid) * HIDDEN + h * HEAD_D;
        const float* QbB = QbA + 8 * HIDDEN;
#pragma unroll
        for (int ks = 0; ks < 4; ks++) {
            int c = ks * 16 + 2 * tg;
            qa[mt][ks][0] = packh2(QbA[c] * 0.125f,     QbA[c + 1] * 0.125f);
            qa[mt][ks][1] = packh2(QbB[c] * 0.125f,     QbB[c + 1] * 0.125f);
            qa[mt][ks][2] = packh2(QbA[c + 8] * 0.125f, QbA[c + 9] * 0.125f);
            qa[mt][ks][3] = packh2(QbB[c + 8] * 0.125f, QbB[c + 9] * 0.125f);
        }
    }

    float accO[2][8][4];
#pragma unroll
    for (int mt = 0; mt < 2; mt++)
#pragma unroll
        for (int nt = 0; nt < 8; nt++)
#pragma unroll
            for (int r = 0; r < 4; r++) accO[mt][nt][r] = 0.f;
    float mA[2] = {-1e30f, -1e30f}, mB[2] = {-1e30f, -1e30f};
    float lA[2] = {0.f, 0.f}, lB[2] = {0.f, 0.f};

    const int lrow = tid & 63, lhalf = (tid >> 6) * 32;
    const int ntiles = 2 * qblk + 2;
    const int wmin = q0 + warp * 32, wmax = wmin + 31;

    for (int t = 0; t < ntiles; t++) {
        const int j0 = t * 64;
        __syncthreads();
        {   // cooperative K/V tile load -> fp16 smem
            const float* kp = K + (size_t)(j0 + lrow) * KV_DIM + g * HEAD_D + lhalf;
            const float* vp = V + (size_t)(j0 + lrow) * KV_DIM + g * HEAD_D + lhalf;
#pragma unroll
            for (int i = 0; i < 4; i++) {
                float4 k0 = *(const float4*)&kp[i * 8];
                float4 k1 = *(const float4*)&kp[i * 8 + 4];
                float4 v0 = *(const float4*)&vp[i * 8];
                float4 v1 = *(const float4*)&vp[i * 8 + 4];
                *(uint4*)&Ks[lrow][lhalf + i * 8] =
                    make_uint4(packh2(k0.x, k0.y), packh2(k0.z, k0.w), packh2(k1.x, k1.y), packh2(k1.z, k1.w));
                *(uint4*)&Vs[lrow][lhalf + i * 8] =
                    make_uint4(packh2(v0.x, v0.y), packh2(v0.z, v0.w), packh2(v1.x, v1.y), packh2(v1.z, v1.w));
            }
        }
        __syncthreads();
        if (j0 > wmax) continue;

        // S = Q @ K^T : 32 rows x 64 keys
        float accS[2][8][4];
#pragma unroll
        for (int mt = 0; mt < 2; mt++)
#pragma unroll
            for (int nt = 0; nt < 8; nt++)
#pragma unroll
                for (int r = 0; r < 4; r++) accS[mt][nt][r] = 0.f;

#pragma unroll
        for (int ks = 0; ks < 4; ks++) {
#pragma unroll
            for (int np = 0; np < 4; np++) {
                // x4 non-trans: r0=b0@nt(2np), r1=b0@nt(2np+1), r2=b1@nt(2np), r3=b1@nt(2np+1)
                uint32_t r0, r1, r2, r3;
                ldsm4(r0, r1, r2, r3,
                      (uint32_t)__cvta_generic_to_shared(
                          &Ks[np * 16 + (lane & 15)][ks * 16 + (lane >> 4) * 8]));
                uint32_t b0[2] = {r0, r2}, b1[2] = {r1, r3};
                mma_f16(accS[0][2 * np],     qa[0][ks], b0);
                mma_f16(accS[1][2 * np],     qa[1][ks], b0);
                mma_f16(accS[0][2 * np + 1], qa[0][ks], b1);
                mma_f16(accS[1][2 * np + 1], qa[1][ks], b1);
            }
        }

        // causal mask on boundary tiles
        if (j0 + 63 > wmin) {
#pragma unroll
            for (int mt = 0; mt < 2; mt++) {
                int rA = wmin + mt * 16 + gid;
#pragma unroll
                for (int nt = 0; nt < 8; nt++) {
                    int k0 = j0 + nt * 8 + 2 * tg;
                    if (k0     > rA)     accS[mt][nt][0] = -1e30f;
                    if (k0 + 1 > rA)     accS[mt][nt][1] = -1e30f;
                    if (k0     > rA + 8) accS[mt][nt][2] = -1e30f;
                    if (k0 + 1 > rA + 8) accS[mt][nt][3] = -1e30f;
                }
            }
        }

        // online softmax (regs 0/1 = row gid, regs 2/3 = row gid+8)
#pragma unroll
        for (int mt = 0; mt < 2; mt++) {
            float mx0 = -1e30f, mx1 = -1e30f;
#pragma unroll
            for (int nt = 0; nt < 8; nt++) {
                mx0 = fmaxf(mx0, fmaxf(accS[mt][nt][0], accS[mt][nt][1]));
                mx1 = fmaxf(mx1, fmaxf(accS[mt][nt][2], accS[mt][nt][3]));
            }
            mx0 = fmaxf(mx0, __shfl_xor_sync(0xffffffffu, mx0, 1));
            mx0 = fmaxf(mx0, __shfl_xor_sync(0xffffffffu, mx0, 2));
            mx1 = fmaxf(mx1, __shfl_xor_sync(0xffffffffu, mx1, 1));
            mx1 = fmaxf(mx1, __shfl_xor_sync(0xffffffffu, mx1, 2));
            float mn0 = fmaxf(mA[mt], mx0), mn1 = fmaxf(mB[mt], mx1);
            float sc0 = __expf(mA[mt] - mn0), sc1 = __expf(mB[mt] - mn1);
            float s0 = 0.f, s1 = 0.f;
#pragma unroll
            for (int nt = 0; nt < 8; nt++) {
                accS[mt][nt][0] = __expf(accS[mt][nt][0] - mn0);
                accS[mt][nt][1] = __expf(accS[mt][nt][1] - mn0);
                accS[mt][nt][2] = __expf(accS[mt][nt][2] - mn1);
                accS[mt][nt][3] = __expf(accS[mt][nt][3] - mn1);
                s0 += accS[mt][nt][0] + accS[mt][nt][1];
                s1 += accS[mt][nt][2] + accS[mt][nt][3];
            }
            s0 += __shfl_xor_sync(0xffffffffu, s0, 1);
            s0 += __shfl_xor_sync(0xffffffffu, s0, 2);
            s1 += __shfl_xor_sync(0xffffffffu, s1, 1);
            s1 += __shfl_xor_sync(0xffffffffu, s1, 2);
            lA[mt] = lA[mt] * sc0 + s0;
            lB[mt] = lB[mt] * sc1 + s1;
            mA[mt] = mn0; mB[mt] = mn1;
#pragma unroll
            for (int nt = 0; nt < 8; nt++) {
                accO[mt][nt][0] *= sc0; accO[mt][nt][1] *= sc0;
                accO[mt][nt][2] *= sc1; accO[mt][nt][3] *= sc1;
            }
        }

        // O += P @ V. P a-frags = pure packing of accS (m16n8k16 layouts align)
#pragma unroll
        for (int ks = 0; ks < 4; ks++) {
            uint32_t pa[2][4];
#pragma unroll
            for (int mt = 0; mt < 2; mt++) {
                pa[mt][0] = packh2(accS[mt][2 * ks][0],     accS[mt][2 * ks][1]);
                pa[mt][1] = packh2(accS[mt][2 * ks][2],     accS[mt][2 * ks][3]);
                pa[mt][2] = packh2(accS[mt][2 * ks + 1][0], accS[mt][2 * ks + 1][1]);
                pa[mt][3] = packh2(accS[mt][2 * ks + 1][2], accS[mt][2 * ks + 1][3]);
            }
#pragma unroll
            for (int np = 0; np < 4; np++) {
                // x4 trans: frag(dtile 2np) = {r0,r1}, frag(2np+1) = {r2,r3}
                uint32_t r0, r1, r2, r3;
                ldsm4t(r0, r1, r2, r3,
                       (uint32_t)__cvta_generic_to_shared(
                           &Vs[ks * 16 + (lane & 15)][np * 16 + (lane >> 4) * 8]));
                uint32_t b0[2] = {r0, r1}, b1[2] = {r2, r3};
                mma_f16(accO[0][2 * np],     pa[0], b0);
                mma_f16(accO[1][2 * np],     pa[1], b0);
                mma_f16(accO[0][2 * np + 1], pa[0], b1);
                mma_f16(accO[1][2 * np + 1], pa[1], b1);
            }
        }
    }

    // epilogue
#pragma unroll
    for (int mt = 0; mt < 2; mt++) {
        float inv0 = 1.f / lA[mt], inv1 = 1.f / lB[mt];
        float* Ob = O + (size_t)(q0 + warp * 32 + mt * 16 + gid) * HIDDEN + h * HEAD_D;
#pragma unroll
        for (int nt = 0; nt < 8; nt++) {
            int c = nt * 8 + 2 * tg;
            *(float2*)&Ob[c]              = make_float2(accO[mt][nt][0] * inv0, accO[mt][nt][1] * inv0);
            *(float2*)&Ob[8 * HIDDEN + c] = make_float2(accO[mt][nt][2] * inv1, accO[mt][nt][3] * inv1);
        }
    }
}

// ---------------------------------------------------------------------------
extern "C" void kernel_launch(void* const* d_in, const int* in_sizes, int n_in,
                              void* d_out, int out_size)
{
    const float* x  = (const float*)d_in[0];
    const float* Wq = (const float*)d_in[2];
    const float* bq = (const float*)d_in[3];
    const float* Wk = (const float*)d_in[4];
    const float* bk = (const float*)d_in[5];
    const float* Wv = (const float*)d_in[6];
    const float* bv = (const float*)d_in[7];
    const float* Wo = (const float*)d_in[8];
    const float* bo = (const float*)d_in[9];
    float* out = (float*)d_out;

    float* Qb; cudaGetSymbolAddress((void**)&Qb, g_Q);
    float* Kb; cudaGetSymbolAddress((void**)&Kb, g_K);
    float* Vb; cudaGetSymbolAddress((void**)&Vb, g_V);
    float* Ab; cudaGetSymbolAddress((void**)&Ab, g_A);

    h_qkv_kernel<<<dim3(24, SEQ / 128), 256>>>(x, Wq, bq, Qb, Wk, bk, Kb, Wv, bv, Vb);
    flash_h_kernel<<<dim3(SEQ / 128, HEADS), dim3(128)>>>(Qb, Kb, Vb, Ab);
    h_out_kernel<<<dim3(HIDDEN / 128, SEQ / 128), 256>>>(Ab, Wo, bo, out);
}

// round 9
// speedup vs baseline: 2.0658x; 1.2235x over previous
#include <cuda_runtime.h>
#include <cuda_fp16.h>
#include <cstdint>

#define SEQ     2048
#define HIDDEN  2048
#define HEADS   32
#define GROUPS  8
#define HEAD_D  64
#define KV_DIM  512
#define QPG     4

// fp16 scratch (device globals: no allocation allowed)
__device__ __half g_xh[SEQ * HIDDEN];
__device__ __half g_Wqh[HIDDEN * HIDDEN];
__device__ __half g_Wkh[HIDDEN * KV_DIM];
__device__ __half g_Wvh[HIDDEN * KV_DIM];
__device__ __half g_Woh[HIDDEN * HIDDEN];
__device__ float  g_bqs[HIDDEN];
__device__ __half g_Qh[SEQ * HIDDEN];
__device__ __half g_Kh[SEQ * KV_DIM];
__device__ __half g_Vh[SEQ * KV_DIM];
__device__ __half g_Ah[SEQ * HIDDEN];

__device__ __forceinline__ uint32_t packh2(float lo, float hi) {
    __half2 h = __floats2half2_rn(lo, hi);
    return *(uint32_t*)&h;
}
__device__ __forceinline__ void mma_f16(float* c, const uint32_t* a, const uint32_t* b) {
    asm volatile(
        "mma.sync.aligned.m16n8k16.row.col.f32.f16.f16.f32 "
        "{%0,%1,%2,%3}, {%4,%5,%6,%7}, {%8,%9}, {%0,%1,%2,%3};\n"
        : "+f"(c[0]), "+f"(c[1]), "+f"(c[2]), "+f"(c[3])
        : "r"(a[0]), "r"(a[1]), "r"(a[2]), "r"(a[3]), "r"(b[0]), "r"(b[1]));
}
__device__ __forceinline__ void ldsm4(uint32_t& r0, uint32_t& r1, uint32_t& r2, uint32_t& r3, uint32_t a) {
    asm volatile("ldmatrix.sync.aligned.m8n8.x4.shared.b16 {%0,%1,%2,%3}, [%4];"
                 : "=r"(r0), "=r"(r1), "=r"(r2), "=r"(r3) : "r"(a));
}
__device__ __forceinline__ void ldsm4t(uint32_t& r0, uint32_t& r1, uint32_t& r2, uint32_t& r3, uint32_t a) {
    asm volatile("ldmatrix.sync.aligned.m8n8.x4.trans.shared.b16 {%0,%1,%2,%3}, [%4];"
                 : "=r"(r0), "=r"(r1), "=r"(r2), "=r"(r3) : "r"(a));
}
__device__ __forceinline__ void cpa16(uint32_t dst, const void* src) {
    asm volatile("cp.async.cg.shared.global [%0], [%1], 16;" :: "r"(dst), "l"(src));
}
__device__ __forceinline__ void cpcommit() { asm volatile("cp.async.commit_group;" ::: "memory"); }
template <int N> __device__ __forceinline__ void cpwait() {
    asm volatile("cp.async.wait_group %0;" :: "n"(N) : "memory");
}

// ---------------- precast kernels ----------------
__global__ __launch_bounds__(256) void cvt_kernel(const float* __restrict__ s,
                                                  __half* __restrict__ d, float sc) {
    int i = (blockIdx.x * 256 + threadIdx.x) * 8;
    float4 a = *(const float4*)&s[i], b = *(const float4*)&s[i + 4];
    *(uint4*)&d[i] = make_uint4(packh2(a.x * sc, a.y * sc), packh2(a.z * sc, a.w * sc),
                                packh2(b.x * sc, b.y * sc), packh2(b.z * sc, b.w * sc));
}
__global__ __launch_bounds__(256) void scaleb_kernel(const float* __restrict__ s, float* __restrict__ d) {
    int i = blockIdx.x * 256 + threadIdx.x;
    d[i] = s[i] * 0.125f;
}

// ---------------------------------------------------------------------------
// pure-fp16 HMMA GEMM, cp.async 3-stage pipeline. C tile [128,128].
// 256 thr, 8 warps (64x32). Stage: A [128][40] halves + B [32][136] halves.
// Row strides 20/68 words (=4 mod 8, odd mult) -> ldmatrix conflict-free.
// ---------------------------------------------------------------------------
#define STG      3
#define STG_H    9472                    // halves per stage (5120 + 4352)
#define GSMEM    (STG * STG_H * 2)       // 56832 bytes

__device__ void hgemm16(const __half* __restrict__ A, const __half* __restrict__ B,
                        const float* __restrict__ bias, void* __restrict__ Cv,
                        int N, int K, int rb, int cb, int outHalf)
{
    extern __shared__ __half hs[];
    const int tid = threadIdx.x, warp = tid >> 5, lane = tid & 31;
    const int gid = lane >> 2, tg = lane & 3;
    const int mBase = (warp & 1) * 64, nBase = (warp >> 1) * 32;
    const uint32_t sbase = (uint32_t)__cvta_generic_to_shared(hs);

    const __half* Ab = A + (size_t)rb * 128 * K;
    const __half* Bb = B + (size_t)cb * 128;

    float acc[4][4][4];
#pragma unroll
    for (int i = 0; i < 4; i++)
#pragma unroll
        for (int j = 0; j < 4; j++)
#pragma unroll
            for (int r = 0; r < 4; r++) acc[i][j][r] = 0.f;

    const int T = K / 32;

    auto issue = [&](int t, int st) {
        uint32_t as = sbase + st * (STG_H * 2);
        uint32_t bs = as + 5120 * 2;
#pragma unroll
        for (int p = 0; p < 2; p++) {   // A: 512 chunks of 8 halves
            int s = tid + p * 256, row = s >> 2, c8 = (s & 3) * 8;
            cpa16(as + (row * 40 + c8) * 2, Ab + (size_t)row * K + t * 32 + c8);
        }
#pragma unroll
        for (int p = 0; p < 2; p++) {   // B: 512 chunks
            int s = tid + p * 256, row = s >> 4, c8 = (s & 15) * 8;
            cpa16(bs + (row * 136 + c8) * 2, Bb + (size_t)(t * 32 + row) * N + c8);
        }
    };

#pragma unroll
    for (int s = 0; s < STG; s++) { issue(s, s); cpcommit(); }

    for (int t = 0; t < T; t++) {
        cpwait<STG - 1>();
        __syncthreads();
        const int st = t % STG;
        const uint32_t as = sbase + st * (STG_H * 2);
        const uint32_t bs = as + 5120 * 2;
#pragma unroll
        for (int k0 = 0; k0 < 32; k0 += 16) {
            uint32_t af[4][4], bf[4][2];
#pragma unroll
            for (int mt = 0; mt < 4; mt++)
                ldsm4(af[mt][0], af[mt][1], af[mt][2], af[mt][3],
                      as + ((mBase + mt * 16 + (lane & 15)) * 40 + k0 + (lane >> 4) * 8) * 2);
#pragma unroll
            for (int np = 0; np < 2; np++)
                ldsm4t(bf[2 * np][0], bf[2 * np][1], bf[2 * np + 1][0], bf[2 * np + 1][1],
                       bs + ((k0 + (lane & 15)) * 136 + nBase + np * 16 + (lane >> 4) * 8) * 2);
#pragma unroll
            for (int mt = 0; mt < 4; mt++)
#pragma unroll
                for (int nt = 0; nt < 4; nt++)
                    mma_f16(acc[mt][nt], af[mt], bf[nt]);
        }
        __syncthreads();
        if (t + STG < T) issue(t + STG, st);
        cpcommit();
    }

#pragma unroll
    for (int mt = 0; mt < 4; mt++) {
#pragma unroll
        for (int nt = 0; nt < 4; nt++) {
            int row = rb * 128 + mBase + mt * 16 + gid;
            int col = cb * 128 + nBase + nt * 8 + tg * 2;
            float bx = bias[col], by = bias[col + 1];
            if (outHalf) {
                __half* C = (__half*)Cv;
                *(uint32_t*)&C[(size_t)row * N + col]       = packh2(acc[mt][nt][0] + bx, acc[mt][nt][1] + by);
                *(uint32_t*)&C[(size_t)(row + 8) * N + col] = packh2(acc[mt][nt][2] + bx, acc[mt][nt][3] + by);
            } else {
                float* C = (float*)Cv;
                *(float2*)&C[(size_t)row * N + col]       = make_float2(acc[mt][nt][0] + bx, acc[mt][nt][1] + by);
                *(float2*)&C[(size_t)(row + 8) * N + col] = make_float2(acc[mt][nt][2] + bx, acc[mt][nt][3] + by);
            }
        }
    }
}

__global__ __launch_bounds__(256) void h_qkv_kernel(
    const float* __restrict__ bk, const float* __restrict__ bv)
{
    int bx = blockIdx.x;
    if (bx < 16)      hgemm16(g_xh, g_Wqh, g_bqs, g_Qh, HIDDEN, HIDDEN, blockIdx.y, bx, 1);
    else if (bx < 20) hgemm16(g_xh, g_Wkh, bk, g_Kh, KV_DIM, HIDDEN, blockIdx.y, bx - 16, 1);
    else              hgemm16(g_xh, g_Wvh, bv, g_Vh, KV_DIM, HIDDEN, blockIdx.y, bx - 20, 1);
}
__global__ __launch_bounds__(256) void h_out_kernel(const float* __restrict__ bo, float* __restrict__ out)
{
    hgemm16(g_Ah, g_Woh, bo, out, HIDDEN, HIDDEN, blockIdx.y, blockIdx.x, 0);
}

// ---------------------------------------------------------------------------
// fp16 flash attention (causal, GQA), fp16 inputs, cp.async K/V loads.
// Q pre-scaled by 1/8 (folded into Wq). grid=(SEQ/128, HEADS), block=128.
// ---------------------------------------------------------------------------
__global__ __launch_bounds__(128) void flash_h_kernel()
{
    __shared__ __half Ks[64][72];
    __shared__ __half Vs[64][72];

    const int qblk = gridDim.x - 1 - blockIdx.x;
    const int h = blockIdx.y, g = h / QPG, q0 = qblk * 128;
    const int tid = threadIdx.x, warp = tid >> 5, lane = tid & 31;
    const int gid = lane >> 2, tg = lane & 3;

    // Q a-frags: direct uint32 loads (already fp16, already scaled)
    uint32_t qa[2][4][4];
#pragma unroll
    for (int mt = 0; mt < 2; mt++) {
        const __half* QbA = g_Qh + (size_t)(q0 + warp * 32 + mt * 16 + gid) * HIDDEN + h * HEAD_D;
        const __half* QbB = QbA + 8 * HIDDEN;
#pragma unroll
        for (int ks = 0; ks < 4; ks++) {
            int c = ks * 16 + 2 * tg;
            qa[mt][ks][0] = *(const uint32_t*)&QbA[c];
            qa[mt][ks][1] = *(const uint32_t*)&QbB[c];
            qa[mt][ks][2] = *(const uint32_t*)&QbA[c + 8];
            qa[mt][ks][3] = *(const uint32_t*)&QbB[c + 8];
        }
    }

    float accO[2][8][4];
#pragma unroll
    for (int mt = 0; mt < 2; mt++)
#pragma unroll
        for (int nt = 0; nt < 8; nt++)
#pragma unroll
            for (int r = 0; r < 4; r++) accO[mt][nt][r] = 0.f;
    float mA[2] = {-1e30f, -1e30f}, mB[2] = {-1e30f, -1e30f};
    float lA[2] = {0.f, 0.f}, lB[2] = {0.f, 0.f};

    const int ntiles = 2 * qblk + 2;
    const int wmin = q0 + warp * 32, wmax = wmin + 31;

    for (int t = 0; t < ntiles; t++) {
        const int j0 = t * 64;
        __syncthreads();
        {   // cp.async K/V tile: 8 chunks of 16B per thread
#pragma unroll
            for (int i = 0; i < 4; i++) {
                int s = tid + i * 128, row = s >> 3, c8 = (s & 7) * 8;
                cpa16((uint32_t)__cvta_generic_to_shared(&Ks[row][c8]),
                      g_Kh + (size_t)(j0 + row) * KV_DIM + g * HEAD_D + c8);
            }
#pragma unroll
            for (int i = 0; i < 4; i++) {
                int s = tid + i * 128, row = s >> 3, c8 = (s & 7) * 8;
                cpa16((uint32_t)__cvta_generic_to_shared(&Vs[row][c8]),
                      g_Vh + (size_t)(j0 + row) * KV_DIM + g * HEAD_D + c8);
            }
            cpcommit();
            cpwait<0>();
        }
        __syncthreads();
        if (j0 > wmax) continue;

        float accS[2][8][4];
#pragma unroll
        for (int mt = 0; mt < 2; mt++)
#pragma unroll
            for (int nt = 0; nt < 8; nt++)
#pragma unroll
                for (int r = 0; r < 4; r++) accS[mt][nt][r] = 0.f;

#pragma unroll
        for (int ks = 0; ks < 4; ks++) {
#pragma unroll
            for (int np = 0; np < 4; np++) {
                uint32_t r0, r1, r2, r3;
                ldsm4(r0, r1, r2, r3,
                      (uint32_t)__cvta_generic_to_shared(
                          &Ks[np * 16 + (lane & 15)][ks * 16 + (lane >> 4) * 8]));
                uint32_t b0[2] = {r0, r2}, b1[2] = {r1, r3};
                mma_f16(accS[0][2 * np],     qa[0][ks], b0);
                mma_f16(accS[1][2 * np],     qa[1][ks], b0);
                mma_f16(accS[0][2 * np + 1], qa[0][ks], b1);
                mma_f16(accS[1][2 * np + 1], qa[1][ks], b1);
            }
        }

        if (j0 + 63 > wmin) {
#pragma unroll
            for (int mt = 0; mt < 2; mt++) {
                int rA = wmin + mt * 16 + gid;
#pragma unroll
                for (int nt = 0; nt < 8; nt++) {
                    int k0 = j0 + nt * 8 + 2 * tg;
                    if (k0     > rA)     accS[mt][nt][0] = -1e30f;
                    if (k0 + 1 > rA)     accS[mt][nt][1] = -1e30f;
                    if (k0     > rA + 8) accS[mt][nt][2] = -1e30f;
                    if (k0 + 1 > rA + 8) accS[mt][nt][3] = -1e30f;
                }
            }
        }

#pragma unroll
        for (int mt = 0; mt < 2; mt++) {
            float mx0 = -1e30f, mx1 = -1e30f;
#pragma unroll
            for (int nt = 0; nt < 8; nt++) {
                mx0 = fmaxf(mx0, fmaxf(accS[mt][nt][0], accS[mt][nt][1]));
                mx1 = fmaxf(mx1, fmaxf(accS[mt][nt][2], accS[mt][nt][3]));
            }
            mx0 = fmaxf(mx0, __shfl_xor_sync(0xffffffffu, mx0, 1));
            mx0 = fmaxf(mx0, __shfl_xor_sync(0xffffffffu, mx0, 2));
            mx1 = fmaxf(mx1, __shfl_xor_sync(0xffffffffu, mx1, 1));
            mx1 = fmaxf(mx1, __shfl_xor_sync(0xffffffffu, mx1, 2));
            float mn0 = fmaxf(mA[mt], mx0), mn1 = fmaxf(mB[mt], mx1);
            float sc0 = __expf(mA[mt] - mn0), sc1 = __expf(mB[mt] - mn1);
            float s0 = 0.f, s1 = 0.f;
#pragma unroll
            for (int nt = 0; nt < 8; nt++) {
                accS[mt][nt][0] = __expf(accS[mt][nt][0] - mn0);
                accS[mt][nt][1] = __expf(accS[mt][nt][1] - mn0);
                accS[mt][nt][2] = __expf(accS[mt][nt][2] - mn1);
                accS[mt][nt][3] = __expf(accS[mt][nt][3] - mn1);
                s0 += accS[mt][nt][0] + accS[mt][nt][1];
                s1 += accS[mt][nt][2] + accS[mt][nt][3];
            }
            s0 += __shfl_xor_sync(0xffffffffu, s0, 1);
            s0 += __shfl_xor_sync(0xffffffffu, s0, 2);
            s1 += __shfl_xor_sync(0xffffffffu, s1, 1);
            s1 += __shfl_xor_sync(0xffffffffu, s1, 2);
            lA[mt] = lA[mt] * sc0 + s0;
            lB[mt] = lB[mt] * sc1 + s1;
            mA[mt] = mn0; mB[mt] = mn1;
#pragma unroll
            for (int nt = 0; nt < 8; nt++) {
                accO[mt][nt][0] *= sc0; accO[mt][nt][1] *= sc0;
                accO[mt][nt][2] *= sc1; accO[mt][nt][3] *= sc1;
            }
        }

#pragma unroll
        for (int ks = 0; ks < 4; ks++) {
            uint32_t pa[2][4];
#pragma unroll
            for (int mt = 0; mt < 2; mt++) {
                pa[mt][0] = packh2(accS[mt][2 * ks][0],     accS[mt][2 * ks][1]);
                pa[mt][1] = packh2(accS[mt][2 * ks][2],     accS[mt][2 * ks][3]);
                pa[mt][2] = packh2(accS[mt][2 * ks + 1][0], accS[mt][2 * ks + 1][1]);
                pa[mt][3] = packh2(accS[mt][2 * ks + 1][2], accS[mt][2 * ks + 1][3]);
            }
#pragma unroll
            for (int np = 0; np < 4; np++) {
                uint32_t r0, r1, r2, r3;
                ldsm4t(r0, r1, r2, r3,
                       (uint32_t)__cvta_generic_to_shared(
                           &Vs[ks * 16 + (lane & 15)][np * 16 + (lane >> 4) * 8]));
                uint32_t b0[2] = {r0, r1}, b1[2] = {r2, r3};
                mma_f16(accO[0][2 * np],     pa[0], b0);
                mma_f16(accO[1][2 * np],     pa[1], b0);
                mma_f16(accO[0][2 * np + 1], pa[0], b1);
                mma_f16(accO[1][2 * np + 1], pa[1], b1);
            }
        }
    }

    // epilogue -> fp16 A
#pragma unroll
    for (int mt = 0; mt < 2; mt++) {
        float inv0 = 1.f / lA[mt], inv1 = 1.f / lB[mt];
        __half* Ob = g_Ah + (size_t)(q0 + warp * 32 + mt * 16 + gid) * HIDDEN + h * HEAD_D;
#pragma unroll
        for (int nt = 0; nt < 8; nt++) {
            int c = nt * 8 + 2 * tg;
            *(uint32_t*)&Ob[c]              = packh2(accO[mt][nt][0] * inv0, accO[mt][nt][1] * inv0);
            *(uint32_t*)&Ob[8 * HIDDEN + c] = packh2(accO[mt][nt][2] * inv1, accO[mt][nt][3] * inv1);
        }
    }
}

// ---------------------------------------------------------------------------
extern "C" void kernel_launch(void* const* d_in, const int* in_sizes, int n_in,
                              void* d_out, int out_size)
{
    const float* x  = (const float*)d_in[0];
    const float* Wq = (const float*)d_in[2];
    const float* bq = (const float*)d_in[3];
    const float* Wk = (const float*)d_in[4];
    const float* bk = (const float*)d_in[5];
    const float* Wv = (const float*)d_in[6];
    const float* bv = (const float*)d_in[7];
    const float* Wo = (const float*)d_in[8];
    const float* bo = (const float*)d_in[9];
    float* out = (float*)d_out;

    __half* xh;  cudaGetSymbolAddress((void**)&xh,  g_xh);
    __half* Wqh; cudaGetSymbolAddress((void**)&Wqh, g_Wqh);
    __half* Wkh; cudaGetSymbolAddress((void**)&Wkh, g_Wkh);
    __half* Wvh; cudaGetSymbolAddress((void**)&Wvh, g_Wvh);
    __half* Woh; cudaGetSymbolAddress((void**)&Woh, g_Woh);
    float*  bqs; cudaGetSymbolAddress((void**)&bqs, g_bqs);

    static int attr_done = 0;
    if (!attr_done) {
        cudaFuncSetAttribute(h_qkv_kernel, cudaFuncAttributeMaxDynamicSharedMemorySize, GSMEM);
        cudaFuncSetAttribute(h_out_kernel, cudaFuncAttributeMaxDynamicSharedMemorySize, GSMEM);
        attr_done = 1;
    }

    cvt_kernel<<<SEQ * HIDDEN / 2048, 256>>>(x, xh, 1.f);
    cvt_kernel<<<HIDDEN * HIDDEN / 2048, 256>>>(Wq, Wqh, 0.125f);
    cvt_kernel<<<HIDDEN * KV_DIM / 2048, 256>>>(Wk, Wkh, 1.f);
    cvt_kernel<<<HIDDEN * KV_DIM / 2048, 256>>>(Wv, Wvh, 1.f);
    cvt_kernel<<<HIDDEN * HIDDEN / 2048, 256>>>(Wo, Woh, 1.f);
    scaleb_kernel<<<HIDDEN / 256, 256>>>(bq, bqs);

    h_qkv_kernel<<<dim3(24, SEQ / 128), 256, GSMEM>>>(bk, bv);
    flash_h_kernel<<<dim3(SEQ / 128, HEADS), dim3(128)>>>();
    h_out_kernel<<<dim3(HIDDEN / 128, SEQ / 128), 256, GSMEM>>>(bo, out);
}